// round 4
// baseline (speedup 1.0000x reference)
#include <cuda_runtime.h>
#include <cuda_bf16.h>

// Problem constants (from reference)
#define NUM_BINS_X 1024
#define NUM_BINS_Y 1024
#define NUM_NODES 2000000
#define NUM_PHYSICAL 2000000
// bsx = bsy = 1.0, origins = 0.0; scale = 1/(1*1*0.1) = 10
#define OUT_SCALE 10.0f
#define SQRT2F 1.41421356237309515f
#define NODES_PER_THREAD 4

__global__ void zero_out_kernel(float4* __restrict__ out) {
    int i = blockIdx.x * blockDim.x + threadIdx.x;
    out[i] = make_float4(0.f, 0.f, 0.f, 0.f);
}

__device__ __forceinline__ void red_v4f32(float* p, float a, float b, float c, float d) {
    asm volatile("red.global.add.v4.f32 [%0], {%1, %2, %3, %4};"
                 :: "l"(p), "f"(a), "f"(b), "f"(c), "f"(d) : "memory");
}

// Overlap of bin [b, b+1) with [vmin, vmax], clamped at 0.
// Exactly zero for bins outside the reference's [bl, bh) window.
__device__ __forceinline__ float ovclamp(float b, float vmin, float vmax) {
    return fmaxf(0.0f, fminf(b + 1.0f, vmax) - fmaxf(b, vmin));
}

__device__ __forceinline__ void process_node(
    float x, float y, float nsx, float nsy, float pw, float* __restrict__ out)
{
    float hx = 0.5f * fmaxf(nsx, SQRT2F);
    float hy = 0.5f * fmaxf(nsy, SQRT2F);
    float cx = x + 0.5f * nsx;
    float cy = y + 0.5f * nsy;
    float xmin = cx - hx, xmax = cx + hx;
    float ymin = cy - hy, ymax = cy + hy;

    int blx = max(0, (int)floorf(xmin));
    int bhx = min((int)floorf(xmax) + 1, NUM_BINS_X);
    int bly = max(0, (int)floorf(ymin));
    int bhy = min((int)floorf(ymax) + 1, NUM_BINS_Y);

    int nx = bhx - blx;
    int ny = bhy - bly;
    if (nx <= 0 || ny <= 0) return;

    float dens = (OUT_SCALE * pw) / (4.0f * hx * hy);

    // 16B-aligned segment covering the y-span; branchless slot overlaps.
    int off = bly & 3;
    int segbase = bly & ~3;
    float sb = (float)segbase;
    float o0 = ovclamp(sb + 0.0f, ymin, ymax);
    float o1 = ovclamp(sb + 1.0f, ymin, ymax);
    float o2 = ovclamp(sb + 2.0f, ymin, ymax);
    float o3 = ovclamp(sb + 3.0f, ymin, ymax);
    bool two_segs = (off + ny) > 4;   // span crosses into second 16B segment
    float o4 = 0.f, o5 = 0.f, o6 = 0.f;
    if (two_segs) {
        o4 = ovclamp(sb + 4.0f, ymin, ymax);
        o5 = ovclamp(sb + 5.0f, ymin, ymax);
        o6 = ovclamp(sb + 6.0f, ymin, ymax);
        // slot 7 unreachable: off+ny-1 <= 6
    }

    for (int kx = 0; kx < nx; ++kx) {
        float bx = (float)(blx + kx);
        float ovx = fminf(bx + 1.0f, xmax) - fmaxf(bx, xmin);
        float c = dens * ovx;
        float* seg = out + (blx + kx) * NUM_BINS_Y + segbase;
        red_v4f32(seg, c * o0, c * o1, c * o2, c * o3);
        if (two_segs)
            red_v4f32(seg + 4, c * o4, c * o5, c * o6, 0.0f);
    }
}

__global__ __launch_bounds__(256) void pin_util_kernel(
    const float4* __restrict__ posx4,
    const float4* __restrict__ posy4,
    const float4* __restrict__ nsx4,
    const float4* __restrict__ nsy4,
    const float4* __restrict__ pw4,
    float* __restrict__ out)
{
    int t = blockIdx.x * 256 + threadIdx.x;          // one thread = 4 nodes
    if (t * NODES_PER_THREAD >= NUM_PHYSICAL) return;

    float4 px = posx4[t];
    float4 py = posy4[t];
    float4 sx = nsx4[t];
    float4 sy = nsy4[t];
    float4 w  = pw4[t];

    process_node(px.x, py.x, sx.x, sy.x, w.x, out);
    process_node(px.y, py.y, sx.y, sy.y, w.y, out);
    process_node(px.z, py.z, sx.z, sy.z, w.z, out);
    process_node(px.w, py.w, sx.w, sy.w, w.w, out);
}

extern "C" void kernel_launch(void* const* d_in, const int* in_sizes, int n_in,
                              void* d_out, int out_size) {
    const float* pos  = (const float*)d_in[0];
    const float* nsx  = (const float*)d_in[1];
    const float* nsy  = (const float*)d_in[2];
    const float* pw   = (const float*)d_in[3];
    float* out = (float*)d_out;

    // out_size = 1024*1024; zero it (poisoned by harness)
    int n4 = (NUM_BINS_X * NUM_BINS_Y) / 4;           // 262144
    zero_out_kernel<<<n4 / 256, 256>>>((float4*)out);

    int nthreads = NUM_PHYSICAL / NODES_PER_THREAD;   // 500000 (divisible by 4)
    int grid = (nthreads + 255) / 256;                // 1954
    pin_util_kernel<<<grid, 256>>>(
        (const float4*)pos,
        (const float4*)(pos + NUM_NODES),
        (const float4*)nsx,
        (const float4*)nsy,
        (const float4*)pw,
        out);
}

// round 5
// speedup vs baseline: 1.0218x; 1.0218x over previous
#include <cuda_runtime.h>
#include <cuda_bf16.h>

// Problem constants (from reference)
#define NUM_BINS_X 1024
#define NUM_BINS_Y 1024
#define NUM_NODES 2000000
#define NUM_PHYSICAL 2000000
// bsx = bsy = 1.0, origins = 0.0; scale = 1/(1*1*0.1) = 10
#define OUT_SCALE 10.0f
#define SQRT2F 1.41421356237309515f

__global__ void zero_out_kernel(float4* __restrict__ out) {
    int i = blockIdx.x * blockDim.x + threadIdx.x;
    out[i] = make_float4(0.f, 0.f, 0.f, 0.f);
}

__device__ __forceinline__ void red_v4f32(float* p, float a, float b, float c, float d) {
    asm volatile("red.global.add.v4.f32 [%0], {%1, %2, %3, %4};"
                 :: "l"(p), "f"(a), "f"(b), "f"(c), "f"(d) : "memory");
}

// Overlap of bin [b, b+1) with [vmin, vmax], clamped at 0.
// Exactly zero outside the reference's [bl, bh) window.
__device__ __forceinline__ float ovclamp(float b, float vmin, float vmax) {
    return fmaxf(0.0f, fminf(b + 1.0f, vmax) - fmaxf(b, vmin));
}

__global__ __launch_bounds__(256) void pin_util_kernel(
    const float* __restrict__ pos,
    const float* __restrict__ node_size_x,
    const float* __restrict__ node_size_y,
    const float* __restrict__ pin_weights,
    float* __restrict__ out)
{
    int i = blockIdx.x * 256 + threadIdx.x;
    if (i >= NUM_PHYSICAL) return;

    float nsx = node_size_x[i];
    float nsy = node_size_y[i];
    float x   = pos[i];
    float y   = pos[NUM_NODES + i];
    float pw  = pin_weights[i];

    float hx = 0.5f * fmaxf(nsx, SQRT2F);
    float hy = 0.5f * fmaxf(nsy, SQRT2F);
    float cx = x + 0.5f * nsx;
    float cy = y + 0.5f * nsy;
    float xmin = cx - hx, xmax = cx + hx;
    float ymin = cy - hy, ymax = cy + hy;

    // bin_size = 1.0, origin = 0.0 -> exact floor math
    int blx = max(0, (int)floorf(xmin));
    int bly = max(0, (int)floorf(ymin));
    int bhy = min((int)floorf(ymax) + 1, NUM_BINS_Y);
    int nx  = min((int)floorf(xmax) + 1, NUM_BINS_X) - blx;   // 1..3 always
    int ny  = bhy - bly;

    float dens = (OUT_SCALE * pw) / (4.0f * hx * hy);

    // 16B-aligned segment covering the y-span; branchless slot overlaps.
    int off = bly & 3;
    int segbase = bly & ~3;
    float sb = (float)segbase;
    float o0 = ovclamp(sb + 0.0f, ymin, ymax);
    float o1 = ovclamp(sb + 1.0f, ymin, ymax);
    float o2 = ovclamp(sb + 2.0f, ymin, ymax);
    float o3 = ovclamp(sb + 3.0f, ymin, ymax);
    bool two_segs = (off + ny) > 4;          // span crosses into second segment
    float o4 = 0.f, o5 = 0.f, o6 = 0.f;
    if (two_segs) {
        o4 = ovclamp(sb + 4.0f, ymin, ymax);
        o5 = ovclamp(sb + 5.0f, ymin, ymax);
        o6 = ovclamp(sb + 6.0f, ymin, ymax);
        // slot 7 unreachable: off+ny-1 <= 6
    }

    float* seg0 = out + blx * NUM_BINS_Y + segbase;
    float fblx = (float)blx;

    // Fully unrolled, predicated x-loop (nx <= 3): REDs issue back-to-back,
    // no loop-control overhead between them.
    #pragma unroll
    for (int kx = 0; kx < 3; ++kx) {
        float bx = fblx + (float)kx;
        float ovx = fminf(bx + 1.0f, xmax) - fmaxf(bx, xmin);
        float c = dens * ovx;
        float* seg = seg0 + kx * NUM_BINS_Y;
        if (kx < nx) {
            red_v4f32(seg, c * o0, c * o1, c * o2, c * o3);
            if (two_segs)
                red_v4f32(seg + 4, c * o4, c * o5, c * o6, 0.0f);
        }
    }
}

extern "C" void kernel_launch(void* const* d_in, const int* in_sizes, int n_in,
                              void* d_out, int out_size) {
    const float* pos  = (const float*)d_in[0];
    const float* nsx  = (const float*)d_in[1];
    const float* nsy  = (const float*)d_in[2];
    const float* pw   = (const float*)d_in[3];
    float* out = (float*)d_out;

    // out_size = 1024*1024; zero it (poisoned by harness)
    int n4 = (NUM_BINS_X * NUM_BINS_Y) / 4;           // 262144
    zero_out_kernel<<<n4 / 256, 256>>>((float4*)out);

    int grid = (NUM_PHYSICAL + 255) / 256;            // 7813
    pin_util_kernel<<<grid, 256>>>(pos, nsx, nsy, pw, out);
}